// round 15
// baseline (speedup 1.0000x reference)
#include <cuda_runtime.h>
#include <cstdint>

#define N_ATOMS_MAX 50000
#define CDIM 64
#define ROW  (3 * CDIM)   // 192 floats per atom

// Scratch accumulator (38.4 MB) — static __device__ per harness rules.
__device__ float g_agg[N_ATOMS_MAX * ROW];

typedef unsigned long long u64;

// ---- packed f32x2 helpers (sm_103a) ---------------------------------------
__device__ __forceinline__ u64 pack2(float a, float b) {
    u64 r; asm("mov.b64 %0, {%1, %2};" : "=l"(r) : "f"(a), "f"(b)); return r;
}
__device__ __forceinline__ void unpack2(u64 v, float& a, float& b) {
    asm("mov.b64 {%0, %1}, %2;" : "=f"(a), "=f"(b) : "l"(v));
}
__device__ __forceinline__ u64 fma2(u64 a, u64 b, u64 c) {
    u64 r; asm("fma.rn.f32x2 %0, %1, %2, %3;" : "=l"(r) : "l"(a), "l"(b), "l"(c)); return r;
}

// ---------------------------------------------------------------------------
// Pair kernel (unchanged — measured at the LTS byte cap, ~114 us).
// 16 threads per pair; each thread owns 4 channels (float4).
//   ix[p,x,c] = (p3[j,x,c] + d3[p,x]) * i1[p,c]  --red.add--> g_agg[i,x,c]
// ---------------------------------------------------------------------------
__global__ void pair_kernel(const int* __restrict__ ind,
                            const float* __restrict__ p3,
                            const float* __restrict__ i1,
                            const float* __restrict__ d3,
                            float* __restrict__ agg,
                            int n_pairs)
{
    int t = blockIdx.x * blockDim.x + threadIdx.x;
    int pair = t >> 4;
    if (pair >= n_pairs) return;
    int lane = t & 15;                   // channel group: 4 channels each

    int ai = ind[2 * pair + 0];          // destination atom i
    int aj = ind[2 * pair + 1];          // source atom j

    float4 g = *reinterpret_cast<const float4*>(i1 + (size_t)pair * CDIM + lane * 4);

    float dv[3];
    dv[0] = d3[3 * pair + 0];
    dv[1] = d3[3 * pair + 1];
    dv[2] = d3[3 * pair + 2];

    const float4* pj = reinterpret_cast<const float4*>(p3 + (size_t)aj * ROW);
    float4*       pa = reinterpret_cast<float4*>(agg + (size_t)ai * ROW);

#pragma unroll
    for (int x = 0; x < 3; x++) {
        float4 v = pj[x * 16 + lane];
        float dx = dv[x];
        float r0 = (v.x + dx) * g.x;
        float r1 = (v.y + dx) * g.y;
        float r2 = (v.z + dx) * g.z;
        float r3 = (v.w + dx) * g.w;
        asm volatile("red.global.add.v4.f32 [%0], {%1, %2, %3, %4};"
                     :: "l"(pa + x * 16 + lane),
                        "f"(r0), "f"(r1), "f"(r2), "f"(r3)
                     : "memory");
    }
}

// ---------------------------------------------------------------------------
// Epilogue v5: R7's best-measured tile (8d x 3row, 256 threads, 32 atoms)
// with __launch_bounds__(256, 5) to lift occupancy from 4 -> 5 blocks/SM.
// Per c-iter: 2x LDS.128 (w) + 3x LDS.32 (sA, broadcast) -> 12 FFMA2.
// ---------------------------------------------------------------------------
#define ATOMS_PER_BLOCK 32

__global__ void __launch_bounds__(256, 5) gemm_kernel(
    const float* __restrict__ agg,
    const float* __restrict__ W,
    float* __restrict__ p3_new,
    float* __restrict__ dotted,
    int n_atoms)
{
    __shared__ __align__(16) float sWT[CDIM][CDIM + 4];           // stride 68: rows 16B-aligned
    __shared__ __align__(16) float sA[ATOMS_PER_BLOCK][ROW + 4];  // stride 196: conflict-free

    int tid = threadIdx.x;           // 0..255
    int a0  = blockIdx.x * ATOMS_PER_BLOCK;

    // stage W transposed: sWT[c][d] = W[d*64+c]
    for (int kk = tid; kk < CDIM * CDIM; kk += 256) {
        int d = kk >> 6, c = kk & 63;
        sWT[c][d] = W[kk];
    }
    // stage 32 agg rows (float4)
    {
        const float4* src = reinterpret_cast<const float4*>(agg);
        for (int kk = tid; kk < ATOMS_PER_BLOCK * (ROW / 4); kk += 256) {
            int la = kk / (ROW / 4);
            int e4 = kk - la * (ROW / 4);
            int a  = a0 + la;
            float4 v = (a < n_atoms) ? src[(size_t)a * (ROW / 4) + e4]
                                     : make_float4(0.f, 0.f, 0.f, 0.f);
            *reinterpret_cast<float4*>(&sA[la][e4 * 4]) = v;
        }
    }
    __syncthreads();

    int la = tid >> 3;               // local atom 0..31
    int d0 = (tid & 7) * 8;          // this thread's 8 output channels
    int a  = a0 + la;

    u64 acc[3][4];
#pragma unroll
    for (int x = 0; x < 3; x++)
#pragma unroll
        for (int kk = 0; kk < 4; kk++) acc[x][kk] = 0ull;

#pragma unroll 8
    for (int c = 0; c < CDIM; c++) {
        const ulonglong2* wr = reinterpret_cast<const ulonglong2*>(&sWT[c][d0]);
        ulonglong2 wa = wr[0];       // w pairs d0..d0+3
        ulonglong2 wb = wr[1];       // w pairs d0+4..d0+7

        float av0 = sA[la][c];
        float av1 = sA[la][CDIM + c];
        float av2 = sA[la][2 * CDIM + c];
        u64 aa0 = pack2(av0, av0);
        u64 aa1 = pack2(av1, av1);
        u64 aa2 = pack2(av2, av2);

        acc[0][0] = fma2(aa0, wa.x, acc[0][0]);
        acc[0][1] = fma2(aa0, wa.y, acc[0][1]);
        acc[0][2] = fma2(aa0, wb.x, acc[0][2]);
        acc[0][3] = fma2(aa0, wb.y, acc[0][3]);

        acc[1][0] = fma2(aa1, wa.x, acc[1][0]);
        acc[1][1] = fma2(aa1, wa.y, acc[1][1]);
        acc[1][2] = fma2(aa1, wb.x, acc[1][2]);
        acc[1][3] = fma2(aa1, wb.y, acc[1][3]);

        acc[2][0] = fma2(aa2, wa.x, acc[2][0]);
        acc[2][1] = fma2(aa2, wa.y, acc[2][1]);
        acc[2][2] = fma2(aa2, wb.x, acc[2][2]);
        acc[2][3] = fma2(aa2, wb.y, acc[2][3]);
    }

    if (a >= n_atoms) return;

    float dot[8];
#pragma unroll
    for (int kk = 0; kk < 8; kk++) dot[kk] = 0.f;

#pragma unroll
    for (int x = 0; x < 3; x++) {
        float s[8];
#pragma unroll
        for (int kk = 0; kk < 4; kk++) {
            unpack2(acc[x][kk], s[2 * kk], s[2 * kk + 1]);
            dot[2 * kk]     += s[2 * kk]     * s[2 * kk];
            dot[2 * kk + 1] += s[2 * kk + 1] * s[2 * kk + 1];
        }
        float* out = p3_new + (size_t)a * ROW + x * CDIM + d0;
        *reinterpret_cast<float4*>(out)     = make_float4(s[0], s[1], s[2], s[3]);
        *reinterpret_cast<float4*>(out + 4) = make_float4(s[4], s[5], s[6], s[7]);
    }
    {
        float* out = dotted + (size_t)a * CDIM + d0;
        *reinterpret_cast<float4*>(out)     = make_float4(dot[0], dot[1], dot[2], dot[3]);
        *reinterpret_cast<float4*>(out + 4) = make_float4(dot[4], dot[5], dot[6], dot[7]);
    }
}

// ---------------------------------------------------------------------------
// Inputs (metadata order): ind_2 [P,2] i32, p3 [A,3,64] f32, i1 [P,64] f32,
// d3 [P,3] f32, W [64,64] f32.  Output: p3_new [A,3,64] ++ dotted [A,64].
// ---------------------------------------------------------------------------
extern "C" void kernel_launch(void* const* d_in, const int* in_sizes, int n_in,
                              void* d_out, int out_size)
{
    const int*   ind = (const int*)  d_in[0];
    const float* p3  = (const float*)d_in[1];
    const float* i1  = (const float*)d_in[2];
    const float* d3  = (const float*)d_in[3];
    const float* W   = (const float*)d_in[4];

    int n_pairs = in_sizes[0] / 2;
    int n_atoms = in_sizes[1] / ROW;

    float* p3_new = (float*)d_out;
    float* dotted = (float*)d_out + (size_t)n_atoms * ROW;

    float* agg;
    cudaGetSymbolAddress((void**)&agg, g_agg);

    // 1) zero accumulator
    cudaMemsetAsync(agg, 0, (size_t)n_atoms * ROW * sizeof(float));

    // 2) pair scatter-reduce: 16 threads per pair
    {
        int total = n_pairs * 16;
        int blk = 256;
        pair_kernel<<<(total + blk - 1) / blk, blk>>>(ind, p3, i1, d3, agg, n_pairs);
    }

    // 3) epilogue GEMM + dot
    {
        int blocks = (n_atoms + ATOMS_PER_BLOCK - 1) / ATOMS_PER_BLOCK;
        gemm_kernel<<<blocks, 256>>>(agg, W, p3_new, dotted, n_atoms);
    }
}